// round 9
// baseline (speedup 1.0000x reference)
#include <cuda_runtime.h>
#include <cstdint>

#define L2E 1.44269504088896340736f

// ---------------------------------------------------------------------------
// Scratch (__device__ globals; no allocs allowed)
// ---------------------------------------------------------------------------
__device__ float  g_Wh[8*1024*128];        // [b][n][h*16+d]
__device__ float4 g_p[8*8*1024];           // per (b,h,row): p1, p2, -, -
__device__ float2 g_q[8*8*1024];           // per (b,h,key): q1, q2
__device__ unsigned g_mb[8*1024*32];       // packed adjacency bits
__device__ float  g_patt[4*8192*128];      // partial attention sums per split
__device__ float  g_plsum[4*64*1024];      // partial weight sums per split
// packed weight pairs (reduction-dim interleaved -> direct b64 FFMA2 operands)
__device__ unsigned long long g_Wp64[8*64*16];    // [h][ip][d]
__device__ unsigned long long g_w1p64[64*256];    // [ip][c]
__device__ unsigned long long g_w2p64[128*128];   // [kp][c]

__device__ __forceinline__ unsigned long long pk2(float a, float b){
    unsigned long long r;
    asm("mov.b64 %0, {%1, %2};" : "=l"(r) : "f"(a), "f"(b));
    return r;
}
__device__ __forceinline__ void fma2(unsigned long long &d, unsigned long long a, unsigned long long b){
    asm("fma.rn.f32x2 %0, %1, %2, %0;" : "+l"(d) : "l"(a), "l"(b));
}
__device__ __forceinline__ unsigned long long mul2(unsigned long long a, unsigned long long b){
    unsigned long long r;
    asm("mul.rn.f32x2 %0, %1, %2;" : "=l"(r) : "l"(a), "l"(b));
    return r;
}
__device__ __forceinline__ unsigned long long add2(unsigned long long a, unsigned long long b){
    unsigned long long r;
    asm("add.rn.f32x2 %0, %1, %2;" : "=l"(r) : "l"(a), "l"(b));
    return r;
}
__device__ __forceinline__ float2 upk(unsigned long long v){
    float2 r;
    asm("mov.b64 {%0, %1}, %2;" : "=f"(r.x), "=f"(r.y) : "l"(v));
    return r;
}

// ---------------------------------------------------------------------------
// K00: pack weight matrices into reduction-dim-pair layout.
// ---------------------------------------------------------------------------
__global__ void __launch_bounds__(256) k00_pack(const float* __restrict__ W,
                                                const float* __restrict__ w1,
                                                const float* __restrict__ w2)
{
    int i = blockIdx.x*256 + threadIdx.x;
    if (i < 8192){
        int h = i >> 10, rem = i & 1023, ip = rem >> 4, d = rem & 15;
        g_Wp64[i] = pk2(W[h*2048 + (2*ip)*16 + d], W[h*2048 + (2*ip+1)*16 + d]);
        return;
    }
    int j = i - 8192;
    if (j < 16384){
        int ip = j >> 8, c = j & 255;
        g_w1p64[j] = pk2(w1[(2*ip)*256 + c], w1[(2*ip+1)*256 + c]);
        return;
    }
    int k = j - 16384;
    if (k < 16384){
        int kp = k >> 7, c = k & 127;
        g_w2p64[k] = pk2(w2[(2*kp)*128 + c], w2[(2*kp+1)*128 + c]);
    }
}

// ---------------------------------------------------------------------------
// K1: Wh = h@W (packed pairs, FFMA2) + factorized-softmax exp tables
//     + adjacency bit-packing.
// ---------------------------------------------------------------------------
__global__ void __launch_bounds__(128) k1_wh(const float* __restrict__ h,
                                             const float* __restrict__ a,
                                             const int* __restrict__ adj)
{
    __shared__ __align__(16) float hs[8][128];
    __shared__ __align__(16) float ps[8][128];
    __shared__ __align__(16) float qs[8][128];
    const int tid = threadIdx.x;
    const int warp = tid >> 5, lane = tid & 31;
    const int gr0 = blockIdx.x * 8;
    {
        const float4* src = (const float4*)(h + gr0*128);
        float4* dst = (float4*)hs;
        #pragma unroll
        for (int q=0;q<2;q++) dst[q*128 + tid] = src[q*128 + tid];
    }

    // pack adjacency bits for this block's 8 rows (warp w: rows 2w, 2w+1)
    {
        #pragma unroll
        for (int rr=0; rr<2; rr++){
            int grow = gr0 + warp*2 + rr;
            const int* rp = adj + (size_t)grow * 1024;
            unsigned* op  = g_mb + grow * 32;
            #pragma unroll 4
            for (int wd=0; wd<32; wd++){
                unsigned v = __ballot_sync(0xffffffffu, rp[wd*32 + lane] != 0);
                if (lane == 0) op[wd] = v;
            }
        }
    }

    __syncthreads();
    const int hh = tid >> 4, d = tid & 15;
    const unsigned long long* wp = g_Wp64 + hh*1024 + d;
    unsigned long long acc[8];
    #pragma unroll
    for (int r=0;r<8;r++) acc[r] = 0ull;
    #pragma unroll 4
    for (int ip2=0; ip2<32; ip2++){
        unsigned long long wv0 = __ldg(wp + ip2*32);
        unsigned long long wv1 = __ldg(wp + ip2*32 + 16);
        #pragma unroll
        for (int r=0;r<8;r++){
            ulonglong2 hv = *(const ulonglong2*)&hs[r][ip2*4];
            fma2(acc[r], hv.x, wv0);
            fma2(acc[r], hv.y, wv1);
        }
    }
    const float asrc = __ldg(a + hh*32 + d);
    const float adst = __ldg(a + hh*32 + 16 + d);
    #pragma unroll
    for (int r=0;r<8;r++){
        float2 v = upk(acc[r]);
        float val = v.x + v.y;
        g_Wh[(gr0+r)*128 + tid] = val;
        ps[r][tid] = val*asrc;
        qs[r][tid] = val*adst;
    }
    __syncthreads();

    if (tid < 64){
        const int rr = tid >> 3, hh2 = tid & 7;
        const float4* pp = (const float4*)&ps[rr][hh2*16];
        const float4* qq = (const float4*)&qs[rr][hh2*16];
        float4 a0=pp[0], a1=pp[1], a2=pp[2], a3=pp[3];
        float4 b0=qq[0], b1=qq[1], b2=qq[2], b3=qq[3];
        float si = ((a0.x+a0.y)+(a0.z+a0.w)) + ((a1.x+a1.y)+(a1.z+a1.w))
                 + ((a2.x+a2.y)+(a2.z+a2.w)) + ((a3.x+a3.y)+(a3.z+a3.w));
        float sj = ((b0.x+b0.y)+(b0.z+b0.w)) + ((b1.x+b1.y)+(b1.z+b1.w))
                 + ((b2.x+b2.y)+(b2.z+b2.w)) + ((b3.x+b3.y)+(b3.z+b3.w));
        si *= L2E; sj *= L2E;
        const int b  = gr0 >> 10;
        const int n0 = gr0 & 1023;
        const int idx = (b*8 + hh2)*1024 + n0 + rr;
        g_p[idx] = make_float4(exp2f(si), exp2f(0.2f*si), 0.f, 0.f);
        g_q[idx] = make_float2(exp2f(sj), exp2f(0.2f*sj));
    }
}

// ---------------------------------------------------------------------------
// K2: fused masked-softmax attention; fmax-form weights; 2 rows/lane.
// Block: 64 rows x 4 heads x 256 keys (4-way key split).
// qt pre-packed as duplicated u64 pairs (no pack MOVs in inner loop).
// ---------------------------------------------------------------------------
__global__ void __launch_bounds__(256, 3) k2_attn()
{
    __shared__ __align__(16) float Whs[128][64];
    __shared__ __align__(16) unsigned long long qt1[4][128];
    __shared__ __align__(16) unsigned long long qt2[4][128];
    __shared__ unsigned mbits[64][9];
    const int tid  = threadIdx.x;
    const int warp = tid >> 5, lane = tid & 31;
    const int hw = warp & 3, grp = warp >> 2;
    const int nt = blockIdx.x;
    const int hb = blockIdx.y & 1, sp = blockIdx.y >> 1;   // sp in [0,4)
    const int b  = blockIdx.z;
    const int h    = hb*4 + hw;
    const int row0 = nt*64 + lane;
    const int row1 = row0 + 32;
    const int key0 = sp*256;

    {
        #pragma unroll
        for (int q=0;q<2;q++){
            int lin = q*256 + tid;
            int rr = lin >> 3, ww = lin & 7;
            mbits[rr][ww] = g_mb[(b*1024 + nt*64 + rr)*32 + sp*8 + ww];
        }
    }

    const float4 pva = g_p[(b*8+h)*1024 + row0];
    const float4 pvb = g_p[(b*8+h)*1024 + row1];
    const unsigned long long P1 = pk2(pva.x, pvb.x);
    const unsigned long long P2 = pk2(pva.y, pvb.y);

    unsigned long long acc0[8], acc1[8];
    #pragma unroll
    for (int j=0;j<8;j++){ acc0[j] = 0ull; acc1[j] = 0ull; }
    unsigned long long Lp = 0ull;                      // (lsum0, lsum1)

    const int bhq = b*8 + hb*4;
    #pragma unroll
    for (int mt=0; mt<2; mt++){
        __syncthreads();
        {
            const float* base = g_Wh + ((size_t)(b<<10))*128 + hb*64;
            #pragma unroll
            for (int q=0;q<8;q++){
                int lin = q*256 + tid;
                int r = lin >> 4, c4 = lin & 15;
                int key = key0 + mt*64 + ((r < 64) ? r : r + 64);
                ((float4*)Whs)[lin] = ((const float4*)(base + key*128))[c4];
            }
            #pragma unroll
            for (int q=0;q<2;q++){
                int lin = q*256 + tid;
                int hl = lin >> 7, k128 = lin & 127;
                int key = key0 + mt*64 + ((k128 < 64) ? k128 : k128 + 64);
                float2 qv = g_q[(bhq+hl)*1024 + key];
                qt1[hl][k128] = pk2(qv.x, qv.x);
                qt2[hl][k128] = pk2(qv.y, qv.y);
            }
        }
        __syncthreads();
        const unsigned long long* q1p = &qt1[hw][grp*64];
        const unsigned long long* q2p = &qt2[hw][grp*64];
        const float*  wb = &Whs[grp*64][0] + hw*16;
        #pragma unroll
        for (int k=0;k<2;k++){
            unsigned mw0 = mbits[lane][grp*4 + mt*2 + k];
            unsigned mw1 = mbits[lane+32][grp*4 + mt*2 + k];
            #pragma unroll
            for (int j=0;j<32;j++){
                int m = k*32 + j;
                unsigned long long A = mul2(P1, q1p[m]);
                unsigned long long B = mul2(P2, q2p[m]);
                float2 Af = upk(A), Bf = upk(B);
                float wa  = fmaxf(Af.x, Bf.x);
                float wbv = fmaxf(Af.y, Bf.y);
                wa  = (mw0 & (1u<<j)) ? wa  : 0.f;
                wbv = (mw1 & (1u<<j)) ? wbv : 0.f;
                Lp = add2(Lp, pk2(wa, wbv));
                unsigned long long wwa = pk2(wa, wa);
                unsigned long long wwb = pk2(wbv, wbv);
                const ulonglong2* wv = (const ulonglong2*)(wb + m*64);
                ulonglong2 v0 = wv[0];
                ulonglong2 v1 = wv[1];
                ulonglong2 v2 = wv[2];
                ulonglong2 v3 = wv[3];
                fma2(acc0[0], v0.x, wwa);
                fma2(acc0[1], v0.y, wwa);
                fma2(acc0[2], v1.x, wwa);
                fma2(acc0[3], v1.y, wwa);
                fma2(acc0[4], v2.x, wwa);
                fma2(acc0[5], v2.y, wwa);
                fma2(acc0[6], v3.x, wwa);
                fma2(acc0[7], v3.y, wwa);
                fma2(acc1[0], v0.x, wwb);
                fma2(acc1[1], v0.y, wwb);
                fma2(acc1[2], v1.x, wwb);
                fma2(acc1[3], v1.y, wwb);
                fma2(acc1[4], v2.x, wwb);
                fma2(acc1[5], v2.y, wwb);
                fma2(acc1[6], v3.x, wwb);
                fma2(acc1[7], v3.y, wwb);
            }
        }
    }

    // combine the two key-half groups through smem (alias onto Whs)
    __syncthreads();
    unsigned long long (*red)[64][9] = (unsigned long long(*)[64][9])Whs;
    float2 Ls = upk(Lp);
    if (grp == 1){
        #pragma unroll
        for (int j=0;j<8;j++){
            red[hw][lane][j]    = acc0[j];
            red[hw][lane+32][j] = acc1[j];
        }
        red[hw][lane][8]    = pk2(Ls.x, 0.f);
        red[hw][lane+32][8] = pk2(Ls.y, 0.f);
    }
    __syncthreads();
    if (grp == 0){
        float lsum0 = Ls.x + upk(red[hw][lane][8]).x;
        float lsum1 = Ls.y + upk(red[hw][lane+32][8]).x;
        g_plsum[(sp*64 + b*8 + h)*1024 + row0] = lsum0;
        g_plsum[(sp*64 + b*8 + h)*1024 + row1] = lsum1;
        float* out0 = g_patt + ((size_t)((sp<<13) + (b<<10) + row0))*128 + h*16;
        float* out1 = g_patt + ((size_t)((sp<<13) + (b<<10) + row1))*128 + h*16;
        #pragma unroll
        for (int j=0;j<4;j++){
            float2 pa0 = upk(acc0[j*2]);
            float2 pa1 = upk(acc0[j*2+1]);
            float2 pb0 = upk(red[hw][lane][j*2]);
            float2 pb1 = upk(red[hw][lane][j*2+1]);
            ((float4*)out0)[j] = make_float4(pa0.x+pb0.x, pa0.y+pb0.y,
                                             pa1.x+pb1.x, pa1.y+pb1.y);
        }
        #pragma unroll
        for (int j=0;j<4;j++){
            float2 pa0 = upk(acc1[j*2]);
            float2 pa1 = upk(acc1[j*2+1]);
            float2 pb0 = upk(red[hw][lane+32][j*2]);
            float2 pb1 = upk(red[hw][lane+32][j*2+1]);
            ((float4*)out1)[j] = make_float4(pa0.x+pb0.x, pa0.y+pb0.y,
                                             pa1.x+pb1.x, pa1.y+pb1.y);
        }
    }
}

// ---------------------------------------------------------------------------
// K3: combine attention partials + LN1 -> FFN -> LN2.
// 128 threads x 16 rows, grid 512. Each thread owns ONE colpair for 16 rows:
// weight L2 streaming halves vs 8-row blocks. LN stages: 8 threads/row.
// ---------------------------------------------------------------------------
__global__ void __launch_bounds__(128) k3_ffn(
    const float* __restrict__ h,
    const float* __restrict__ ln1g, const float* __restrict__ ln1b,
    const float* __restrict__ b1,
    const float* __restrict__ b2,
    const float* __restrict__ ln2g, const float* __restrict__ ln2b,
    float* __restrict__ out)
{
    __shared__ __align__(16) float hcs[16][128];
    __shared__ __align__(16) float mids[16][256];
    const int tid = threadIdx.x;
    const int gr0 = blockIdx.x * 16;
    const int r16 = tid >> 3, l8 = tid & 7;    // row 0..15, colgroup 0..7 (16 cols, == head)
    const int gr = gr0 + r16;

    // Stage 1: combine split partials, divide, add residual, LN1 -> hcs
    float x[16];
    {
        const int bb = gr >> 10, rw = gr & 1023;
        float lsum = 0.f;
        #pragma unroll
        for (int s=0;s<4;s++) lsum += g_plsum[(s*64 + bb*8 + l8)*1024 + rw];
        float inv = (lsum > 0.f) ? __fdividef(1.f, lsum) : 0.f;

        float4 av[4];
        #pragma unroll
        for (int q=0;q<4;q++) av[q] = make_float4(0,0,0,0);
        #pragma unroll
        for (int s=0;s<4;s++){
            const float4* pp = (const float4*)(g_patt + ((size_t)((s<<13) + gr))*128 + l8*16);
            #pragma unroll
            for (int q=0;q<4;q++){
                float4 t = pp[q];
                av[q].x+=t.x; av[q].y+=t.y; av[q].z+=t.z; av[q].w+=t.w;
            }
        }
        const float4* hp = (const float4*)(h + gr*128 + l8*16);
        #pragma unroll
        for (int q=0;q<4;q++){
            float4 hv = hp[q];
            x[q*4+0] = fmaf(av[q].x, inv, hv.x);
            x[q*4+1] = fmaf(av[q].y, inv, hv.y);
            x[q*4+2] = fmaf(av[q].z, inv, hv.z);
            x[q*4+3] = fmaf(av[q].w, inv, hv.w);
        }
    }
    float s=0.f, sq=0.f;
    #pragma unroll
    for (int i=0;i<16;i++){ s += x[i]; sq = fmaf(x[i],x[i],sq); }
    #pragma unroll
    for (int o=4;o;o>>=1){
        s  += __shfl_xor_sync(0xffffffffu, s,  o);
        sq += __shfl_xor_sync(0xffffffffu, sq, o);
    }
    float mu   = s * 0.0078125f;
    float var  = fmaf(sq, 0.0078125f, -mu*mu);
    float rstd = rsqrtf(var + 1e-5f);
    #pragma unroll
    for (int i=0;i<16;i++){
        int c = l8*16 + i;
        hcs[r16][c] = (x[i]-mu)*rstd*__ldg(ln1g+c) + __ldg(ln1b+c);
    }
    __syncthreads();

    // Stage 2: mids = relu(hc @ w1 + b1). thread = colpair cp, ALL 16 rows.
    {
        const int cp = tid;                 // cols 2cp, 2cp+1
        unsigned long long acc[16][2];
        #pragma unroll
        for (int rr=0;rr<16;rr++){ acc[rr][0]=0ull; acc[rr][1]=0ull; }
        #pragma unroll 2
        for (int ip2=0; ip2<32; ip2++){
            ulonglong2 w0 = __ldg((const ulonglong2*)(g_w1p64 + (2*ip2  )*256 + 2*cp));
            ulonglong2 w1v= __ldg((const ulonglong2*)(g_w1p64 + (2*ip2+1)*256 + 2*cp));
            #pragma unroll
            for (int rr=0;rr<16;rr++){
                ulonglong2 hv = *(const ulonglong2*)&hcs[rr][ip2*4];
                fma2(acc[rr][0], hv.x, w0.x);
                fma2(acc[rr][1], hv.x, w0.y);
                fma2(acc[rr][0], hv.y, w1v.x);
                fma2(acc[rr][1], hv.y, w1v.y);
            }
        }
        float2 bb = __ldg((const float2*)b1 + cp);
        #pragma unroll
        for (int rr=0;rr<16;rr++){
            float2 s0 = upk(acc[rr][0]);
            float2 s1 = upk(acc[rr][1]);
            float m0 = fmaxf(s0.x + s0.y + bb.x, 0.f);
            float m1 = fmaxf(s1.x + s1.y + bb.y, 0.f);
            *(float2*)&mids[rr][cp*2] = make_float2(m0, m1);
        }
    }
    __syncthreads();

    // Stage 3: z = hc + mid @ w2 + b2 (in place). thread = (row-half, colpair).
    {
        const int rg = tid >> 6;            // 0..1 -> rows rg*8 .. +7
        const int cp = tid & 63;            // cols 2cp, 2cp+1
        unsigned long long acc[8][2];
        #pragma unroll
        for (int rr=0;rr<8;rr++){ acc[rr][0]=0ull; acc[rr][1]=0ull; }
        #pragma unroll 4
        for (int kp2=0; kp2<64; kp2++){
            ulonglong2 w0 = __ldg((const ulonglong2*)(g_w2p64 + (2*kp2  )*128 + 2*cp));
            ulonglong2 w1v= __ldg((const ulonglong2*)(g_w2p64 + (2*kp2+1)*128 + 2*cp));
            #pragma unroll
            for (int rr=0;rr<8;rr++){
                ulonglong2 mv = *(const ulonglong2*)&mids[rg*8+rr][kp2*4];
                fma2(acc[rr][0], mv.x, w0.x);
                fma2(acc[rr][1], mv.x, w0.y);
                fma2(acc[rr][0], mv.y, w1v.x);
                fma2(acc[rr][1], mv.y, w1v.y);
            }
        }
        float2 bb = __ldg((const float2*)b2 + cp);
        #pragma unroll
        for (int rr=0;rr<8;rr++){
            int rw = rg*8 + rr;
            float2 hv = *(const float2*)&hcs[rw][cp*2];
            float2 s0 = upk(acc[rr][0]);
            float2 s1 = upk(acc[rr][1]);
            float z0 = hv.x + s0.x + s0.y + bb.x;
            float z1 = hv.y + s1.x + s1.y + bb.y;
            *(float2*)&hcs[rw][cp*2] = make_float2(z0, z1);
        }
    }
    __syncthreads();

    // Stage 4: LN2 -> out (same 8-threads/row indexing as stage 1)
    float z[16];
    #pragma unroll
    for (int i=0;i<16;i++) z[i] = hcs[r16][l8*16+i];
    float s2=0.f, sq2=0.f;
    #pragma unroll
    for (int i=0;i<16;i++){ s2 += z[i]; sq2 = fmaf(z[i],z[i],sq2); }
    #pragma unroll
    for (int o=4;o;o>>=1){
        s2  += __shfl_xor_sync(0xffffffffu, s2,  o);
        sq2 += __shfl_xor_sync(0xffffffffu, sq2, o);
    }
    float mu2   = s2 * 0.0078125f;
    float var2  = fmaf(sq2, 0.0078125f, -mu2*mu2);
    float rstd2 = rsqrtf(var2 + 1e-5f);
    float t[16];
    #pragma unroll
    for (int i=0;i<16;i++){
        int c = l8*16+i;
        t[i] = (z[i]-mu2)*rstd2*__ldg(ln2g+c) + __ldg(ln2b+c);
    }
    float* op = out + gr*128 + l8*16;
    #pragma unroll
    for (int q=0;q<4;q++){
        ((float4*)op)[q] = make_float4(t[q*4+0],t[q*4+1],t[q*4+2],t[q*4+3]);
    }
}

// ---------------------------------------------------------------------------
extern "C" void kernel_launch(void* const* d_in, const int* in_sizes, int n_in,
                              void* d_out, int out_size)
{
    const float* h    = (const float*)d_in[0];
    const int*   adj  = (const int*  )d_in[1];
    const float* W    = (const float*)d_in[2];
    const float* a    = (const float*)d_in[3];
    const float* ln1g = (const float*)d_in[4];
    const float* ln1b = (const float*)d_in[5];
    const float* w1   = (const float*)d_in[6];
    const float* b1   = (const float*)d_in[7];
    const float* w2   = (const float*)d_in[8];
    const float* b2   = (const float*)d_in[9];
    const float* ln2g = (const float*)d_in[10];
    const float* ln2b = (const float*)d_in[11];
    float* out = (float*)d_out;

    k00_pack<<<160, 256>>>(W, w1, w2);
    k1_wh<<<1024, 128>>>(h, a, adj);
    k2_attn<<<dim3(16, 8, 8), 256>>>();
    k3_ffn<<<512, 128>>>(h, ln1g, ln1b, b1, b2, ln2g, ln2b, out);
}

// round 10
// speedup vs baseline: 1.1848x; 1.1848x over previous
#include <cuda_runtime.h>
#include <cstdint>

#define L2E 1.44269504088896340736f

// ---------------------------------------------------------------------------
// Scratch (__device__ globals; no allocs allowed)
// ---------------------------------------------------------------------------
__device__ float  g_Wh[8*1024*128];        // [b][n][h*16+d]
__device__ float4 g_p[8*8*1024];           // per (b,h,row): p1, p2, -, -
__device__ float2 g_q[8*8*1024];           // per (b,h,key): q1, q2
__device__ unsigned g_mb[8*1024*32];       // packed adjacency bits
__device__ float  g_patt[4*8192*128];      // partial attention sums per split
__device__ float  g_plsum[4*64*1024];      // partial weight sums per split
// packed weight pairs (reduction-dim interleaved -> direct b64 FFMA2 operands)
__device__ unsigned long long g_Wp64[8*64*16];    // [h][ip][d]
__device__ unsigned long long g_w1p64[64*256];    // [ip][c]
__device__ unsigned long long g_w2p64[128*128];   // [kp][c]

__device__ __forceinline__ unsigned long long pk2(float a, float b){
    unsigned long long r;
    asm("mov.b64 %0, {%1, %2};" : "=l"(r) : "f"(a), "f"(b));
    return r;
}
__device__ __forceinline__ void fma2(unsigned long long &d, unsigned long long a, unsigned long long b){
    asm("fma.rn.f32x2 %0, %1, %2, %0;" : "+l"(d) : "l"(a), "l"(b));
}
__device__ __forceinline__ unsigned long long mul2(unsigned long long a, unsigned long long b){
    unsigned long long r;
    asm("mul.rn.f32x2 %0, %1, %2;" : "=l"(r) : "l"(a), "l"(b));
    return r;
}
__device__ __forceinline__ unsigned long long add2(unsigned long long a, unsigned long long b){
    unsigned long long r;
    asm("add.rn.f32x2 %0, %1, %2;" : "=l"(r) : "l"(a), "l"(b));
    return r;
}
__device__ __forceinline__ float2 upk(unsigned long long v){
    float2 r;
    asm("mov.b64 {%0, %1}, %2;" : "=f"(r.x), "=f"(r.y) : "l"(v));
    return r;
}

// ---------------------------------------------------------------------------
// K00: pack weight matrices into reduction-dim-pair layout.
// ---------------------------------------------------------------------------
__global__ void __launch_bounds__(256) k00_pack(const float* __restrict__ W,
                                                const float* __restrict__ w1,
                                                const float* __restrict__ w2)
{
    int i = blockIdx.x*256 + threadIdx.x;
    if (i < 8192){
        int h = i >> 10, rem = i & 1023, ip = rem >> 4, d = rem & 15;
        g_Wp64[i] = pk2(W[h*2048 + (2*ip)*16 + d], W[h*2048 + (2*ip+1)*16 + d]);
        return;
    }
    int j = i - 8192;
    if (j < 16384){
        int ip = j >> 8, c = j & 255;
        g_w1p64[j] = pk2(w1[(2*ip)*256 + c], w1[(2*ip+1)*256 + c]);
        return;
    }
    int k = j - 16384;
    if (k < 16384){
        int kp = k >> 7, c = k & 127;
        g_w2p64[k] = pk2(w2[(2*kp)*128 + c], w2[(2*kp+1)*128 + c]);
    }
}

// ---------------------------------------------------------------------------
// K0: pack adjacency into bitmask words.
// ---------------------------------------------------------------------------
__global__ void __launch_bounds__(256) k0_pack(const int* __restrict__ adj)
{
    const int gw   = blockIdx.x * 8 + (threadIdx.x >> 5);
    const int lane = threadIdx.x & 31;
    const int* rp  = adj + (size_t)gw * 1024;
    unsigned* op   = g_mb + gw * 32;
    #pragma unroll
    for (int w = 0; w < 32; w++){
        unsigned v = __ballot_sync(0xffffffffu, rp[w*32 + lane] != 0);
        if (lane == 0) op[w] = v;
    }
}

// ---------------------------------------------------------------------------
// K1: Wh = h@W (packed pairs, FFMA2) + factorized-softmax exp tables.
// ---------------------------------------------------------------------------
__global__ void __launch_bounds__(128) k1_wh(const float* __restrict__ h,
                                             const float* __restrict__ a)
{
    __shared__ __align__(16) float hs[8][128];
    __shared__ __align__(16) float ps[8][128];
    __shared__ __align__(16) float qs[8][128];
    const int tid = threadIdx.x;
    const int gr0 = blockIdx.x * 8;
    {
        const float4* src = (const float4*)(h + gr0*128);
        float4* dst = (float4*)hs;
        #pragma unroll
        for (int q=0;q<2;q++) dst[q*128 + tid] = src[q*128 + tid];
    }
    __syncthreads();
    const int hh = tid >> 4, d = tid & 15;
    const unsigned long long* wp = g_Wp64 + hh*1024 + d;
    unsigned long long acc[8];
    #pragma unroll
    for (int r=0;r<8;r++) acc[r] = 0ull;
    #pragma unroll 4
    for (int ip2=0; ip2<32; ip2++){
        unsigned long long wv0 = __ldg(wp + ip2*32);
        unsigned long long wv1 = __ldg(wp + ip2*32 + 16);
        #pragma unroll
        for (int r=0;r<8;r++){
            ulonglong2 hv = *(const ulonglong2*)&hs[r][ip2*4];
            fma2(acc[r], hv.x, wv0);
            fma2(acc[r], hv.y, wv1);
        }
    }
    const float asrc = __ldg(a + hh*32 + d);
    const float adst = __ldg(a + hh*32 + 16 + d);
    #pragma unroll
    for (int r=0;r<8;r++){
        float2 v = upk(acc[r]);
        float val = v.x + v.y;
        g_Wh[(gr0+r)*128 + tid] = val;
        ps[r][tid] = val*asrc;
        qs[r][tid] = val*adst;
    }
    __syncthreads();

    if (tid < 64){
        const int rr = tid >> 3, hh2 = tid & 7;
        const float4* pp = (const float4*)&ps[rr][hh2*16];
        const float4* qq = (const float4*)&qs[rr][hh2*16];
        float4 a0=pp[0], a1=pp[1], a2=pp[2], a3=pp[3];
        float4 b0=qq[0], b1=qq[1], b2=qq[2], b3=qq[3];
        float si = ((a0.x+a0.y)+(a0.z+a0.w)) + ((a1.x+a1.y)+(a1.z+a1.w))
                 + ((a2.x+a2.y)+(a2.z+a2.w)) + ((a3.x+a3.y)+(a3.z+a3.w));
        float sj = ((b0.x+b0.y)+(b0.z+b0.w)) + ((b1.x+b1.y)+(b1.z+b1.w))
                 + ((b2.x+b2.y)+(b2.z+b2.w)) + ((b3.x+b3.y)+(b3.z+b3.w));
        si *= L2E; sj *= L2E;
        const int b  = gr0 >> 10;
        const int n0 = gr0 & 1023;
        const int idx = (b*8 + hh2)*1024 + n0 + rr;
        g_p[idx] = make_float4(exp2f(si), exp2f(0.2f*si), 0.f, 0.f);
        g_q[idx] = make_float2(exp2f(sj), exp2f(0.2f*sj));
    }
}

// ---------------------------------------------------------------------------
// K2: fused masked-softmax attention; fmax-form; 4 rows/lane.
// Block: 128 rows x 4 heads x 256 keys (4-way key split).
// grid (8 ntiles, 8 = sp*2+hb, 8 batches) x 256 threads; 2 CTAs/SM.
// Lane owns rows lane+{0,32,64,96}: each Whs broadcast feeds 32 FFMA2.
// ---------------------------------------------------------------------------
__global__ void __launch_bounds__(256, 2) k2_attn()
{
    __shared__ __align__(16) float Whs[128][64];
    __shared__ __align__(16) float2 qt[4][128];
    __shared__ unsigned mbits[128][9];
    const int tid  = threadIdx.x;
    const int warp = tid >> 5, lane = tid & 31;
    const int hw = warp & 3, grp = warp >> 2;
    const int nt = blockIdx.x;
    const int hb = blockIdx.y & 1, sp = blockIdx.y >> 1;   // sp in [0,4)
    const int b  = blockIdx.z;
    const int h    = hb*4 + hw;
    const int row0 = nt*128 + lane;

    // mask words: 128 rows x 8 words (this split's 256 keys)
    {
        #pragma unroll
        for (int q=0;q<4;q++){
            int lin = q*256 + tid;
            int rr = lin >> 3, ww = lin & 7;
            mbits[rr][ww] = g_mb[(b*1024 + nt*128 + rr)*32 + sp*8 + ww];
        }
    }

    const float4 pv0 = g_p[(b*8+h)*1024 + row0];
    const float4 pv1 = g_p[(b*8+h)*1024 + row0 + 32];
    const float4 pv2 = g_p[(b*8+h)*1024 + row0 + 64];
    const float4 pv3 = g_p[(b*8+h)*1024 + row0 + 96];
    const unsigned long long P1_01 = pk2(pv0.x, pv1.x);
    const unsigned long long P1_23 = pk2(pv2.x, pv3.x);
    const unsigned long long P2_01 = pk2(pv0.y, pv1.y);
    const unsigned long long P2_23 = pk2(pv2.y, pv3.y);

    unsigned long long acc[4][8];
    #pragma unroll
    for (int i=0;i<4;i++)
        #pragma unroll
        for (int j=0;j<8;j++) acc[i][j] = 0ull;
    unsigned long long Lp01 = 0ull, Lp23 = 0ull;

    const int bhq = b*8 + hb*4;
    #pragma unroll
    for (int mt=0; mt<2; mt++){
        __syncthreads();
        {
            const float* base = g_Wh + ((size_t)(b*1024 + sp*256 + mt*128))*128 + hb*64;
            #pragma unroll
            for (int q=0;q<8;q++){
                int lin = q*256 + tid;
                int r = lin >> 4, c4 = lin & 15;
                ((float4*)Whs)[lin] = ((const float4*)(base + r*128))[c4];
            }
            #pragma unroll
            for (int q=0;q<2;q++){
                int lin = q*256 + tid;
                int hl = lin >> 7, k128 = lin & 127;
                qt[hl][k128] = g_q[(bhq+hl)*1024 + sp*256 + mt*128 + k128];
            }
        }
        __syncthreads();
        const float2* qp = &qt[hw][0];
        const float*  wb = &Whs[0][0] + hw*16;
        #pragma unroll
        for (int k=0;k<2;k++){
            int ww = mt*4 + grp*2 + k;
            unsigned mw0 = mbits[lane     ][ww];
            unsigned mw1 = mbits[lane + 32][ww];
            unsigned mw2 = mbits[lane + 64][ww];
            unsigned mw3 = mbits[lane + 96][ww];
            #pragma unroll
            for (int j=0;j<32;j++){
                int m = grp*64 + k*32 + j;
                float2 q = qp[m];
                unsigned long long Q1 = pk2(q.x, q.x);
                unsigned long long Q2 = pk2(q.y, q.y);
                unsigned long long A01 = mul2(P1_01, Q1);
                unsigned long long A23 = mul2(P1_23, Q1);
                unsigned long long B01 = mul2(P2_01, Q2);
                unsigned long long B23 = mul2(P2_23, Q2);
                float2 a01 = upk(A01), a23 = upk(A23);
                float2 b01 = upk(B01), b23 = upk(B23);
                float w0 = fmaxf(a01.x, b01.x);
                float w1 = fmaxf(a01.y, b01.y);
                float w2 = fmaxf(a23.x, b23.x);
                float w3 = fmaxf(a23.y, b23.y);
                w0 = (mw0 & (1u<<j)) ? w0 : 0.f;
                w1 = (mw1 & (1u<<j)) ? w1 : 0.f;
                w2 = (mw2 & (1u<<j)) ? w2 : 0.f;
                w3 = (mw3 & (1u<<j)) ? w3 : 0.f;
                Lp01 = add2(Lp01, pk2(w0, w1));
                Lp23 = add2(Lp23, pk2(w2, w3));
                unsigned long long ww0 = pk2(w0, w0);
                unsigned long long ww1 = pk2(w1, w1);
                unsigned long long ww2 = pk2(w2, w2);
                unsigned long long ww3 = pk2(w3, w3);
                const ulonglong2* wv = (const ulonglong2*)(wb + m*64);
                ulonglong2 v0 = wv[0];
                ulonglong2 v1 = wv[1];
                ulonglong2 v2 = wv[2];
                ulonglong2 v3 = wv[3];
                fma2(acc[0][0], v0.x, ww0); fma2(acc[0][1], v0.y, ww0);
                fma2(acc[0][2], v1.x, ww0); fma2(acc[0][3], v1.y, ww0);
                fma2(acc[0][4], v2.x, ww0); fma2(acc[0][5], v2.y, ww0);
                fma2(acc[0][6], v3.x, ww0); fma2(acc[0][7], v3.y, ww0);
                fma2(acc[1][0], v0.x, ww1); fma2(acc[1][1], v0.y, ww1);
                fma2(acc[1][2], v1.x, ww1); fma2(acc[1][3], v1.y, ww1);
                fma2(acc[1][4], v2.x, ww1); fma2(acc[1][5], v2.y, ww1);
                fma2(acc[1][6], v3.x, ww1); fma2(acc[1][7], v3.y, ww1);
                fma2(acc[2][0], v0.x, ww2); fma2(acc[2][1], v0.y, ww2);
                fma2(acc[2][2], v1.x, ww2); fma2(acc[2][3], v1.y, ww2);
                fma2(acc[2][4], v2.x, ww2); fma2(acc[2][5], v2.y, ww2);
                fma2(acc[2][6], v3.x, ww2); fma2(acc[2][7], v3.y, ww2);
                fma2(acc[3][0], v0.x, ww3); fma2(acc[3][1], v0.y, ww3);
                fma2(acc[3][2], v1.x, ww3); fma2(acc[3][3], v1.y, ww3);
                fma2(acc[3][4], v2.x, ww3); fma2(acc[3][5], v2.y, ww3);
                fma2(acc[3][6], v3.x, ww3); fma2(acc[3][7], v3.y, ww3);
            }
        }
    }

    // combine the two key-half groups through smem (alias onto Whs), 2 passes
    float2 L01 = upk(Lp01), L23 = upk(Lp23);
    float ls[4] = { L01.x, L01.y, L23.x, L23.y };
    unsigned long long (*red)[64][9] = (unsigned long long(*)[64][9])Whs;
    #pragma unroll
    for (int pass=0; pass<2; pass++){
        __syncthreads();
        if (grp == 1){
            #pragma unroll
            for (int j=0;j<8;j++){
                red[hw][lane][j]    = acc[pass*2  ][j];
                red[hw][lane+32][j] = acc[pass*2+1][j];
            }
            red[hw][lane][8]    = pk2(ls[pass*2  ], 0.f);
            red[hw][lane+32][8] = pk2(ls[pass*2+1], 0.f);
        }
        __syncthreads();
        if (grp == 0){
            #pragma unroll
            for (int j=0;j<8;j++){
                acc[pass*2  ][j] = add2(acc[pass*2  ][j], red[hw][lane][j]);
                acc[pass*2+1][j] = add2(acc[pass*2+1][j], red[hw][lane+32][j]);
            }
            ls[pass*2  ] += upk(red[hw][lane][8]).x;
            ls[pass*2+1] += upk(red[hw][lane+32][8]).x;
        }
    }
    if (grp == 0){
        #pragma unroll
        for (int i=0;i<4;i++){
            int row = row0 + i*32;
            g_plsum[(sp*64 + b*8 + h)*1024 + row] = ls[i];
            float* outp = g_patt + ((size_t)((sp<<13) + (b<<10) + row))*128 + h*16;
            #pragma unroll
            for (int j=0;j<4;j++){
                float2 p0 = upk(acc[i][j*2]);
                float2 p1 = upk(acc[i][j*2+1]);
                ((float4*)outp)[j] = make_float4(p0.x, p0.y, p1.x, p1.y);
            }
        }
    }
}

// ---------------------------------------------------------------------------
// K3: combine attention partials + LN1 -> FFN -> LN2.
// 128 threads x 8 rows, grid 1024. Weights via coalesced LDG.128.
// ---------------------------------------------------------------------------
__global__ void __launch_bounds__(128) k3_ffn(
    const float* __restrict__ h,
    const float* __restrict__ ln1g, const float* __restrict__ ln1b,
    const float* __restrict__ b1,
    const float* __restrict__ b2,
    const float* __restrict__ ln2g, const float* __restrict__ ln2b,
    float* __restrict__ out)
{
    __shared__ __align__(16) float hcs[8][128];
    __shared__ __align__(16) float mids[8][256];
    const int tid = threadIdx.x;
    const int gr0 = blockIdx.x * 8;
    const int r = tid >> 4, l16 = tid & 15;
    const int gr = gr0 + r;

    // Stage 1: combine split partials, divide, add residual, LN1 -> hcs
    float x[8];
    {
        const int head = l16 >> 1;
        const int bb = gr >> 10, rw = gr & 1023;
        float lsum = 0.f;
        #pragma unroll
        for (int s=0;s<4;s++) lsum += g_plsum[(s*64 + bb*8 + head)*1024 + rw];
        float inv = (lsum > 0.f) ? __fdividef(1.f, lsum) : 0.f;

        float4 a0 = make_float4(0,0,0,0), a1 = make_float4(0,0,0,0);
        #pragma unroll
        for (int s=0;s<4;s++){
            const float4* pp = (const float4*)(g_patt + ((size_t)((s<<13) + gr))*128 + l16*8);
            float4 t0 = pp[0], t1 = pp[1];
            a0.x+=t0.x; a0.y+=t0.y; a0.z+=t0.z; a0.w+=t0.w;
            a1.x+=t1.x; a1.y+=t1.y; a1.z+=t1.z; a1.w+=t1.w;
        }
        const float4* hp = (const float4*)(h + gr*128 + l16*8);
        float4 h0 = hp[0], h1 = hp[1];
        x[0]=fmaf(a0.x,inv,h0.x); x[1]=fmaf(a0.y,inv,h0.y);
        x[2]=fmaf(a0.z,inv,h0.z); x[3]=fmaf(a0.w,inv,h0.w);
        x[4]=fmaf(a1.x,inv,h1.x); x[5]=fmaf(a1.y,inv,h1.y);
        x[6]=fmaf(a1.z,inv,h1.z); x[7]=fmaf(a1.w,inv,h1.w);
    }
    float s=0.f, sq=0.f;
    #pragma unroll
    for (int i=0;i<8;i++){ s += x[i]; sq = fmaf(x[i],x[i],sq); }
    #pragma unroll
    for (int o=8;o;o>>=1){
        s  += __shfl_xor_sync(0xffffffffu, s,  o);
        sq += __shfl_xor_sync(0xffffffffu, sq, o);
    }
    float mu   = s * 0.0078125f;
    float var  = fmaf(sq, 0.0078125f, -mu*mu);
    float rstd = rsqrtf(var + 1e-5f);
    #pragma unroll
    for (int i=0;i<8;i++){
        int c = l16*8 + i;
        hcs[r][c] = (x[i]-mu)*rstd*__ldg(ln1g+c) + __ldg(ln1b+c);
    }
    __syncthreads();

    // Stage 2: mids = relu(hc @ w1 + b1). thread = colpair cp, 8 rows.
    {
        const int cp = tid;                 // cols 2cp, 2cp+1
        unsigned long long acc[8][2];
        #pragma unroll
        for (int rr=0;rr<8;rr++){ acc[rr][0]=0ull; acc[rr][1]=0ull; }
        #pragma unroll 4
        for (int ip2=0; ip2<32; ip2++){
            ulonglong2 w0 = __ldg((const ulonglong2*)(g_w1p64 + (2*ip2  )*256 + 2*cp));
            ulonglong2 w1v= __ldg((const ulonglong2*)(g_w1p64 + (2*ip2+1)*256 + 2*cp));
            #pragma unroll
            for (int rr=0;rr<8;rr++){
                ulonglong2 hv = *(const ulonglong2*)&hcs[rr][ip2*4];
                fma2(acc[rr][0], hv.x, w0.x);
                fma2(acc[rr][1], hv.x, w0.y);
                fma2(acc[rr][0], hv.y, w1v.x);
                fma2(acc[rr][1], hv.y, w1v.y);
            }
        }
        float2 bb = __ldg((const float2*)b1 + cp);
        #pragma unroll
        for (int rr=0;rr<8;rr++){
            float2 s0 = upk(acc[rr][0]);
            float2 s1 = upk(acc[rr][1]);
            float m0 = fmaxf(s0.x + s0.y + bb.x, 0.f);
            float m1 = fmaxf(s1.x + s1.y + bb.y, 0.f);
            *(float2*)&mids[rr][cp*2] = make_float2(m0, m1);
        }
    }
    __syncthreads();

    // Stage 3: z = hc + mid @ w2 + b2 (in place). thread = (row-half, colpair).
    {
        const int rg = tid >> 6;            // 0..1 -> rows rg*4 .. +3
        const int cp = tid & 63;            // cols 2cp, 2cp+1
        unsigned long long acc[4][2];
        #pragma unroll
        for (int rr=0;rr<4;rr++){ acc[rr][0]=0ull; acc[rr][1]=0ull; }
        #pragma unroll 4
        for (int kp2=0; kp2<64; kp2++){
            ulonglong2 w0 = __ldg((const ulonglong2*)(g_w2p64 + (2*kp2  )*128 + 2*cp));
            ulonglong2 w1v= __ldg((const ulonglong2*)(g_w2p64 + (2*kp2+1)*128 + 2*cp));
            #pragma unroll
            for (int rr=0;rr<4;rr++){
                ulonglong2 mv = *(const ulonglong2*)&mids[rg*4+rr][kp2*4];
                fma2(acc[rr][0], mv.x, w0.x);
                fma2(acc[rr][1], mv.x, w0.y);
                fma2(acc[rr][0], mv.y, w1v.x);
                fma2(acc[rr][1], mv.y, w1v.y);
            }
        }
        float2 bb = __ldg((const float2*)b2 + cp);
        #pragma unroll
        for (int rr=0;rr<4;rr++){
            int rw = rg*4 + rr;
            float2 hv = *(const float2*)&hcs[rw][cp*2];
            float2 s0 = upk(acc[rr][0]);
            float2 s1 = upk(acc[rr][1]);
            float z0 = hv.x + s0.x + s0.y + bb.x;
            float z1 = hv.y + s1.x + s1.y + bb.y;
            *(float2*)&hcs[rw][cp*2] = make_float2(z0, z1);
        }
    }
    __syncthreads();

    // Stage 4: LN2 -> out
    float z[8];
    #pragma unroll
    for (int i=0;i<8;i++) z[i] = hcs[r][l16*8+i];
    float s2=0.f, sq2=0.f;
    #pragma unroll
    for (int i=0;i<8;i++){ s2 += z[i]; sq2 = fmaf(z[i],z[i],sq2); }
    #pragma unroll
    for (int o=8;o;o>>=1){
        s2  += __shfl_xor_sync(0xffffffffu, s2,  o);
        sq2 += __shfl_xor_sync(0xffffffffu, sq2, o);
    }
    float mu2   = s2 * 0.0078125f;
    float var2  = fmaf(sq2, 0.0078125f, -mu2*mu2);
    float rstd2 = rsqrtf(var2 + 1e-5f);
    float t[8];
    #pragma unroll
    for (int i=0;i<8;i++){
        int c = l16*8+i;
        t[i] = (z[i]-mu2)*rstd2*__ldg(ln2g+c) + __ldg(ln2b+c);
    }
    float* op = out + gr*128 + l16*8;
    ((float4*)op)[0] = make_float4(t[0],t[1],t[2],t[3]);
    ((float4*)op)[1] = make_float4(t[4],t[5],t[6],t[7]);
}

// ---------------------------------------------------------------------------
extern "C" void kernel_launch(void* const* d_in, const int* in_sizes, int n_in,
                              void* d_out, int out_size)
{
    const float* h    = (const float*)d_in[0];
    const int*   adj  = (const int*  )d_in[1];
    const float* W    = (const float*)d_in[2];
    const float* a    = (const float*)d_in[3];
    const float* ln1g = (const float*)d_in[4];
    const float* ln1b = (const float*)d_in[5];
    const float* w1   = (const float*)d_in[6];
    const float* b1   = (const float*)d_in[7];
    const float* w2   = (const float*)d_in[8];
    const float* b2   = (const float*)d_in[9];
    const float* ln2g = (const float*)d_in[10];
    const float* ln2b = (const float*)d_in[11];
    float* out = (float*)d_out;

    k00_pack<<<160, 256>>>(W, w1, w2);
    k0_pack<<<1024, 256>>>(adj);
    k1_wh<<<1024, 128>>>(h, a);
    k2_attn<<<dim3(8, 8, 8), 256>>>();
    k3_ffn<<<1024, 128>>>(h, ln1g, ln1b, b1, b2, ln2g, ln2b, out);
}

// round 11
// speedup vs baseline: 1.2384x; 1.0452x over previous
#include <cuda_runtime.h>
#include <cstdint>

#define L2E 1.44269504088896340736f

// ---------------------------------------------------------------------------
// Scratch (__device__ globals; no allocs allowed)
// ---------------------------------------------------------------------------
__device__ float  g_Wh[8*1024*128];        // [b][n][h*16+d]
__device__ float4 g_p[8*8*1024];           // per (b,h,row): p1, p2, thr, -
__device__ float2 g_q[8*8*1024];           // per (b,h,key): q1, q2
__device__ unsigned g_mb[8*1024*32];       // packed adjacency bits
__device__ float  g_patt[4*8192*128];      // partial attention sums per split
__device__ float  g_plsum[4*64*1024];      // partial weight sums per split
// packed weight pairs (reduction-dim interleaved -> direct b64 FFMA2 operands)
__device__ unsigned long long g_Wp64[8*64*16];    // [h][ip][d]
__device__ unsigned long long g_w1p64[64*256];    // [ip][c]
__device__ unsigned long long g_w2p64[128*128];   // [kp][c]

__device__ __forceinline__ unsigned long long pk2(float a, float b){
    unsigned long long r;
    asm("mov.b64 %0, {%1, %2};" : "=l"(r) : "f"(a), "f"(b));
    return r;
}
__device__ __forceinline__ void fma2(unsigned long long &d, unsigned long long a, unsigned long long b){
    asm("fma.rn.f32x2 %0, %1, %2, %0;" : "+l"(d) : "l"(a), "l"(b));
}
__device__ __forceinline__ float2 upk(unsigned long long v){
    float2 r;
    asm("mov.b64 {%0, %1}, %2;" : "=f"(r.x), "=f"(r.y) : "l"(v));
    return r;
}

// ---------------------------------------------------------------------------
// K00: pack weight matrices into reduction-dim-pair layout.
// ---------------------------------------------------------------------------
__global__ void __launch_bounds__(256) k00_pack(const float* __restrict__ W,
                                                const float* __restrict__ w1,
                                                const float* __restrict__ w2)
{
    int i = blockIdx.x*256 + threadIdx.x;
    if (i < 8192){
        int h = i >> 10, rem = i & 1023, ip = rem >> 4, d = rem & 15;
        g_Wp64[i] = pk2(W[h*2048 + (2*ip)*16 + d], W[h*2048 + (2*ip+1)*16 + d]);
        return;
    }
    int j = i - 8192;
    if (j < 16384){
        int ip = j >> 8, c = j & 255;
        g_w1p64[j] = pk2(w1[(2*ip)*256 + c], w1[(2*ip+1)*256 + c]);
        return;
    }
    int k = j - 16384;
    if (k < 16384){
        int kp = k >> 7, c = k & 127;
        g_w2p64[k] = pk2(w2[(2*kp)*128 + c], w2[(2*kp+1)*128 + c]);
    }
}

// ---------------------------------------------------------------------------
// K1: Wh = h@W (packed pairs, FFMA2) + factorized-softmax exp tables
//     + adjacency bit-packing (merged former k0; overlaps its HBM read).
// grid 1024 x 128; block = 8 rows.
// ---------------------------------------------------------------------------
__global__ void __launch_bounds__(128) k1_wh(const float* __restrict__ h,
                                             const float* __restrict__ a,
                                             const int* __restrict__ adj)
{
    __shared__ __align__(16) float hs[8][128];
    __shared__ __align__(16) float ps[8][128];
    __shared__ __align__(16) float qs[8][128];
    const int tid = threadIdx.x;
    const int warp = tid >> 5, lane = tid & 31;
    const int gr0 = blockIdx.x * 8;
    {
        const float4* src = (const float4*)(h + gr0*128);
        float4* dst = (float4*)hs;
        #pragma unroll
        for (int q=0;q<2;q++) dst[q*128 + tid] = src[q*128 + tid];
    }

    // pack adjacency bits for this block's 8 rows (warp w: rows 2w, 2w+1)
    {
        #pragma unroll
        for (int rr=0; rr<2; rr++){
            int grow = gr0 + warp*2 + rr;
            const int* rp = adj + (size_t)grow * 1024;
            unsigned* op  = g_mb + grow * 32;
            #pragma unroll 4
            for (int wd=0; wd<32; wd++){
                unsigned v = __ballot_sync(0xffffffffu, rp[wd*32 + lane] != 0);
                if (lane == 0) op[wd] = v;
            }
        }
    }

    __syncthreads();
    const int hh = tid >> 4, d = tid & 15;
    const unsigned long long* wp = g_Wp64 + hh*1024 + d;
    unsigned long long acc[8];
    #pragma unroll
    for (int r=0;r<8;r++) acc[r] = 0ull;
    #pragma unroll 4
    for (int ip2=0; ip2<32; ip2++){
        unsigned long long wv0 = __ldg(wp + ip2*32);
        unsigned long long wv1 = __ldg(wp + ip2*32 + 16);
        #pragma unroll
        for (int r=0;r<8;r++){
            ulonglong2 hv = *(const ulonglong2*)&hs[r][ip2*4];
            fma2(acc[r], hv.x, wv0);
            fma2(acc[r], hv.y, wv1);
        }
    }
    const float asrc = __ldg(a + hh*32 + d);
    const float adst = __ldg(a + hh*32 + 16 + d);
    #pragma unroll
    for (int r=0;r<8;r++){
        float2 v = upk(acc[r]);
        float val = v.x + v.y;
        g_Wh[(gr0+r)*128 + tid] = val;
        ps[r][tid] = val*asrc;
        qs[r][tid] = val*adst;
    }
    __syncthreads();

    if (tid < 64){
        const int rr = tid >> 3, hh2 = tid & 7;
        const float4* pp = (const float4*)&ps[rr][hh2*16];
        const float4* qq = (const float4*)&qs[rr][hh2*16];
        float4 a0=pp[0], a1=pp[1], a2=pp[2], a3=pp[3];
        float4 b0=qq[0], b1=qq[1], b2=qq[2], b3=qq[3];
        float si = ((a0.x+a0.y)+(a0.z+a0.w)) + ((a1.x+a1.y)+(a1.z+a1.w))
                 + ((a2.x+a2.y)+(a2.z+a2.w)) + ((a3.x+a3.y)+(a3.z+a3.w));
        float sj = ((b0.x+b0.y)+(b0.z+b0.w)) + ((b1.x+b1.y)+(b1.z+b1.w))
                 + ((b2.x+b2.y)+(b2.z+b2.w)) + ((b3.x+b3.y)+(b3.z+b3.w));
        si *= L2E; sj *= L2E;
        const int b  = gr0 >> 10;
        const int n0 = gr0 & 1023;
        const int idx = (b*8 + hh2)*1024 + n0 + rr;
        g_p[idx] = make_float4(exp2f(si), exp2f(0.2f*si), exp2f(-si), 0.f);
        g_q[idx] = make_float2(exp2f(sj), exp2f(0.2f*sj));
    }
}

// ---------------------------------------------------------------------------
// K2: fused masked-softmax attention, MUFU-free, 2 rows/lane.
// Block: 64 rows x 4 heads x 256 keys (4-way key split); 8 warps.
// __launch_bounds__(256,3): 3 CTAs/SM (24 warps) -- measured optimum (R6).
// ---------------------------------------------------------------------------
__global__ void __launch_bounds__(256, 3) k2_attn()
{
    __shared__ __align__(16) float Whs[128][64];
    __shared__ __align__(16) float2 qt[4][128];
    __shared__ unsigned mbits[64][9];
    const int tid  = threadIdx.x;
    const int warp = tid >> 5, lane = tid & 31;
    const int hw = warp & 3, grp = warp >> 2;
    const int nt = blockIdx.x;
    const int hb = blockIdx.y & 1, sp = blockIdx.y >> 1;   // sp in [0,4)
    const int b  = blockIdx.z;
    const int h    = hb*4 + hw;
    const int row0 = nt*64 + lane;
    const int row1 = row0 + 32;
    const int key0 = sp*256;

    {
        #pragma unroll
        for (int q=0;q<2;q++){
            int lin = q*256 + tid;
            int rr = lin >> 3, ww = lin & 7;
            mbits[rr][ww] = g_mb[(b*1024 + nt*64 + rr)*32 + sp*8 + ww];
        }
    }

    const float4 pva = g_p[(b*8+h)*1024 + row0];
    const float4 pvb = g_p[(b*8+h)*1024 + row1];
    const float p1a = pva.x, p2a = pva.y, thra = pva.z;
    const float p1b = pvb.x, p2b = pvb.y, thrb = pvb.z;

    unsigned long long acc0[8], acc1[8];
    #pragma unroll
    for (int j=0;j<8;j++){ acc0[j] = 0ull; acc1[j] = 0ull; }
    float lsum0 = 0.f, lsum1 = 0.f;

    const int bhq = b*8 + hb*4;
    #pragma unroll
    for (int mt=0; mt<2; mt++){
        __syncthreads();
        {
            const float* base = g_Wh + ((size_t)(b<<10))*128 + hb*64;
            #pragma unroll
            for (int q=0;q<8;q++){
                int lin = q*256 + tid;
                int r = lin >> 4, c4 = lin & 15;
                int key = key0 + mt*64 + ((r < 64) ? r : r + 64);
                ((float4*)Whs)[lin] = ((const float4*)(base + key*128))[c4];
            }
            #pragma unroll
            for (int q=0;q<2;q++){
                int lin = q*256 + tid;
                int hl = lin >> 7, k128 = lin & 127;
                int key = key0 + mt*64 + ((k128 < 64) ? k128 : k128 + 64);
                qt[hl][k128] = g_q[(bhq+hl)*1024 + key];
            }
        }
        __syncthreads();
        const float2* qp = &qt[hw][grp*64];
        const float*  wb = &Whs[grp*64][0] + hw*16;
        #pragma unroll
        for (int k=0;k<2;k++){
            unsigned mw0 = mbits[lane][grp*4 + mt*2 + k];
            unsigned mw1 = mbits[lane+32][grp*4 + mt*2 + k];
            #pragma unroll
            for (int j=0;j<32;j++){
                int m = k*32 + j;
                float2 q = qp[m];
                const ulonglong2* wv = (const ulonglong2*)(wb + m*64);
                ulonglong2 v0 = wv[0];
                ulonglong2 v1 = wv[1];
                ulonglong2 v2 = wv[2];
                ulonglong2 v3 = wv[3];
                float A0 = p1a*q.x, B0 = p2a*q.y;
                float A1 = p1b*q.x, B1 = p2b*q.y;
                // row 0
                float ta = (q.x >= thra) ? A0 : B0;
                float wa = (mw0 & (1u<<j)) ? ta : 0.f;
                lsum0 += wa;
                unsigned long long wwa = pk2(wa, wa);
                fma2(acc0[0], v0.x, wwa);
                fma2(acc0[1], v0.y, wwa);
                fma2(acc0[2], v1.x, wwa);
                fma2(acc0[3], v1.y, wwa);
                fma2(acc0[4], v2.x, wwa);
                fma2(acc0[5], v2.y, wwa);
                fma2(acc0[6], v3.x, wwa);
                fma2(acc0[7], v3.y, wwa);
                // row 1
                float tb = (q.x >= thrb) ? A1 : B1;
                float wbv = (mw1 & (1u<<j)) ? tb : 0.f;
                lsum1 += wbv;
                unsigned long long wwb = pk2(wbv, wbv);
                fma2(acc1[0], v0.x, wwb);
                fma2(acc1[1], v0.y, wwb);
                fma2(acc1[2], v1.x, wwb);
                fma2(acc1[3], v1.y, wwb);
                fma2(acc1[4], v2.x, wwb);
                fma2(acc1[5], v2.y, wwb);
                fma2(acc1[6], v3.x, wwb);
                fma2(acc1[7], v3.y, wwb);
            }
        }
    }

    __syncthreads();
    unsigned long long (*red)[64][9] = (unsigned long long(*)[64][9])Whs;
    if (grp == 1){
        #pragma unroll
        for (int j=0;j<8;j++){
            red[hw][lane][j]    = acc0[j];
            red[hw][lane+32][j] = acc1[j];
        }
        red[hw][lane][8]    = pk2(lsum0, 0.f);
        red[hw][lane+32][8] = pk2(lsum1, 0.f);
    }
    __syncthreads();
    if (grp == 0){
        lsum0 += upk(red[hw][lane][8]).x;
        lsum1 += upk(red[hw][lane+32][8]).x;
        g_plsum[(sp*64 + b*8 + h)*1024 + row0] = lsum0;
        g_plsum[(sp*64 + b*8 + h)*1024 + row1] = lsum1;
        float* out0 = g_patt + ((size_t)((sp<<13) + (b<<10) + row0))*128 + h*16;
        float* out1 = g_patt + ((size_t)((sp<<13) + (b<<10) + row1))*128 + h*16;
        #pragma unroll
        for (int j=0;j<4;j++){
            float2 pa0 = upk(acc0[j*2]);
            float2 pa1 = upk(acc0[j*2+1]);
            float2 pb0 = upk(red[hw][lane][j*2]);
            float2 pb1 = upk(red[hw][lane][j*2+1]);
            ((float4*)out0)[j] = make_float4(pa0.x+pb0.x, pa0.y+pb0.y,
                                             pa1.x+pb1.x, pa1.y+pb1.y);
        }
        #pragma unroll
        for (int j=0;j<4;j++){
            float2 pa0 = upk(acc1[j*2]);
            float2 pa1 = upk(acc1[j*2+1]);
            float2 pb0 = upk(red[hw][lane+32][j*2]);
            float2 pb1 = upk(red[hw][lane+32][j*2+1]);
            ((float4*)out1)[j] = make_float4(pa0.x+pb0.x, pa0.y+pb0.y,
                                             pa1.x+pb1.x, pa1.y+pb1.y);
        }
    }
}

// ---------------------------------------------------------------------------
// K3: combine attention partials + LN1 -> FFN -> LN2.
// 128 threads x 8 rows, grid 1024. Weights via coalesced LDG.128.
// Stage-2 unroll deepened to 8 for more LDG MLP (latency-bound per R7 ncu).
// ---------------------------------------------------------------------------
__global__ void __launch_bounds__(128) k3_ffn(
    const float* __restrict__ h,
    const float* __restrict__ ln1g, const float* __restrict__ ln1b,
    const float* __restrict__ b1,
    const float* __restrict__ b2,
    const float* __restrict__ ln2g, const float* __restrict__ ln2b,
    float* __restrict__ out)
{
    __shared__ __align__(16) float hcs[8][128];
    __shared__ __align__(16) float mids[8][256];
    const int tid = threadIdx.x;
    const int gr0 = blockIdx.x * 8;
    const int r = tid >> 4, l16 = tid & 15;
    const int gr = gr0 + r;

    // Stage 1: combine split partials, divide, add residual, LN1 -> hcs
    float x[8];
    {
        const int head = l16 >> 1;
        const int bb = gr >> 10, rw = gr & 1023;
        float lsum = 0.f;
        #pragma unroll
        for (int s=0;s<4;s++) lsum += g_plsum[(s*64 + bb*8 + head)*1024 + rw];
        float inv = (lsum > 0.f) ? __fdividef(1.f, lsum) : 0.f;

        float4 a0 = make_float4(0,0,0,0), a1 = make_float4(0,0,0,0);
        #pragma unroll
        for (int s=0;s<4;s++){
            const float4* pp = (const float4*)(g_patt + ((size_t)((s<<13) + gr))*128 + l16*8);
            float4 t0 = pp[0], t1 = pp[1];
            a0.x+=t0.x; a0.y+=t0.y; a0.z+=t0.z; a0.w+=t0.w;
            a1.x+=t1.x; a1.y+=t1.y; a1.z+=t1.z; a1.w+=t1.w;
        }
        const float4* hp = (const float4*)(h + gr*128 + l16*8);
        float4 h0 = hp[0], h1 = hp[1];
        x[0]=fmaf(a0.x,inv,h0.x); x[1]=fmaf(a0.y,inv,h0.y);
        x[2]=fmaf(a0.z,inv,h0.z); x[3]=fmaf(a0.w,inv,h0.w);
        x[4]=fmaf(a1.x,inv,h1.x); x[5]=fmaf(a1.y,inv,h1.y);
        x[6]=fmaf(a1.z,inv,h1.z); x[7]=fmaf(a1.w,inv,h1.w);
    }
    float s=0.f, sq=0.f;
    #pragma unroll
    for (int i=0;i<8;i++){ s += x[i]; sq = fmaf(x[i],x[i],sq); }
    #pragma unroll
    for (int o=8;o;o>>=1){
        s  += __shfl_xor_sync(0xffffffffu, s,  o);
        sq += __shfl_xor_sync(0xffffffffu, sq, o);
    }
    float mu   = s * 0.0078125f;
    float var  = fmaf(sq, 0.0078125f, -mu*mu);
    float rstd = rsqrtf(var + 1e-5f);
    #pragma unroll
    for (int i=0;i<8;i++){
        int c = l16*8 + i;
        hcs[r][c] = (x[i]-mu)*rstd*__ldg(ln1g+c) + __ldg(ln1b+c);
    }
    __syncthreads();

    // Stage 2: mids = relu(hc @ w1 + b1). thread = colpair cp, 8 rows.
    {
        const int cp = tid;                 // cols 2cp, 2cp+1
        unsigned long long acc[8][2];
        #pragma unroll
        for (int rr=0;rr<8;rr++){ acc[rr][0]=0ull; acc[rr][1]=0ull; }
        #pragma unroll 8
        for (int ip2=0; ip2<32; ip2++){
            ulonglong2 w0 = __ldg((const ulonglong2*)(g_w1p64 + (2*ip2  )*256 + 2*cp));
            ulonglong2 w1v= __ldg((const ulonglong2*)(g_w1p64 + (2*ip2+1)*256 + 2*cp));
            #pragma unroll
            for (int rr=0;rr<8;rr++){
                ulonglong2 hv = *(const ulonglong2*)&hcs[rr][ip2*4];
                fma2(acc[rr][0], hv.x, w0.x);
                fma2(acc[rr][1], hv.x, w0.y);
                fma2(acc[rr][0], hv.y, w1v.x);
                fma2(acc[rr][1], hv.y, w1v.y);
            }
        }
        float2 bb = __ldg((const float2*)b1 + cp);
        #pragma unroll
        for (int rr=0;rr<8;rr++){
            float2 s0 = upk(acc[rr][0]);
            float2 s1 = upk(acc[rr][1]);
            float m0 = fmaxf(s0.x + s0.y + bb.x, 0.f);
            float m1 = fmaxf(s1.x + s1.y + bb.y, 0.f);
            *(float2*)&mids[rr][cp*2] = make_float2(m0, m1);
        }
    }
    __syncthreads();

    // Stage 3: z = hc + mid @ w2 + b2 (in place). thread = (row-half, colpair).
    {
        const int rg = tid >> 6;            // 0..1 -> rows rg*4 .. +3
        const int cp = tid & 63;            // cols 2cp, 2cp+1
        unsigned long long acc[4][2];
        #pragma unroll
        for (int rr=0;rr<4;rr++){ acc[rr][0]=0ull; acc[rr][1]=0ull; }
        #pragma unroll 4
        for (int kp2=0; kp2<64; kp2++){
            ulonglong2 w0 = __ldg((const ulonglong2*)(g_w2p64 + (2*kp2  )*128 + 2*cp));
            ulonglong2 w1v= __ldg((const ulonglong2*)(g_w2p64 + (2*kp2+1)*128 + 2*cp));
            #pragma unroll
            for (int rr=0;rr<4;rr++){
                ulonglong2 mv = *(const ulonglong2*)&mids[rg*4+rr][kp2*4];
                fma2(acc[rr][0], mv.x, w0.x);
                fma2(acc[rr][1], mv.x, w0.y);
                fma2(acc[rr][0], mv.y, w1v.x);
                fma2(acc[rr][1], mv.y, w1v.y);
            }
        }
        float2 bb = __ldg((const float2*)b2 + cp);
        #pragma unroll
        for (int rr=0;rr<4;rr++){
            int rw = rg*4 + rr;
            float2 hv = *(const float2*)&hcs[rw][cp*2];
            float2 s0 = upk(acc[rr][0]);
            float2 s1 = upk(acc[rr][1]);
            float z0 = hv.x + s0.x + s0.y + bb.x;
            float z1 = hv.y + s1.x + s1.y + bb.y;
            *(float2*)&hcs[rw][cp*2] = make_float2(z0, z1);
        }
    }
    __syncthreads();

    // Stage 4: LN2 -> out
    float z[8];
    #pragma unroll
    for (int i=0;i<8;i++) z[i] = hcs[r][l16*8+i];
    float s2=0.f, sq2=0.f;
    #pragma unroll
    for (int i=0;i<8;i++){ s2 += z[i]; sq2 = fmaf(z[i],z[i],sq2); }
    #pragma unroll
    for (int o=8;o;o>>=1){
        s2  += __shfl_xor_sync(0xffffffffu, s2,  o);
        sq2 += __shfl_xor_sync(0xffffffffu, sq2, o);
    }
    float mu2   = s2 * 0.0078125f;
    float var2  = fmaf(sq2, 0.0078125f, -mu2*mu2);
    float rstd2 = rsqrtf(var2 + 1e-5f);
    float t[8];
    #pragma unroll
    for (int i=0;i<8;i++){
        int c = l16*8+i;
        t[i] = (z[i]-mu2)*rstd2*__ldg(ln2g+c) + __ldg(ln2b+c);
    }
    float* op = out + gr*128 + l16*8;
    ((float4*)op)[0] = make_float4(t[0],t[1],t[2],t[3]);
    ((float4*)op)[1] = make_float4(t[4],t[5],t[6],t[7]);
}

// ---------------------------------------------------------------------------
extern "C" void kernel_launch(void* const* d_in, const int* in_sizes, int n_in,
                              void* d_out, int out_size)
{
    const float* h    = (const float*)d_in[0];
    const int*   adj  = (const int*  )d_in[1];
    const float* W    = (const float*)d_in[2];
    const float* a    = (const float*)d_in[3];
    const float* ln1g = (const float*)d_in[4];
    const float* ln1b = (const float*)d_in[5];
    const float* w1   = (const float*)d_in[6];
    const float* b1   = (const float*)d_in[7];
    const float* w2   = (const float*)d_in[8];
    const float* b2   = (const float*)d_in[9];
    const float* ln2g = (const float*)d_in[10];
    const float* ln2b = (const float*)d_in[11];
    float* out = (float*)d_out;

    k00_pack<<<160, 256>>>(W, w1, w2);
    k1_wh<<<1024, 128>>>(h, a, adj);
    k2_attn<<<dim3(16, 8, 8), 256>>>();
    k3_ffn<<<1024, 128>>>(h, ln1g, ln1b, b1, b2, ln2g, ln2b, out);
}

// round 12
// speedup vs baseline: 1.2474x; 1.0073x over previous
#include <cuda_runtime.h>
#include <cstdint>

#define L2E 1.44269504088896340736f

// ---------------------------------------------------------------------------
// Scratch (__device__ globals; no allocs allowed)
// ---------------------------------------------------------------------------
__device__ float  g_Wh[8*1024*128];        // [b][n][h*16+d]
__device__ float4 g_p[8*8*1024];           // per (b,h,row): p1, p2, -, -
__device__ float2 g_q[8*8*1024];           // per (b,h,key): q1, q2
__device__ unsigned g_mb[8*1024*32];       // packed adjacency bits
__device__ float  g_patt[4*8192*128];      // partial attention sums per split
__device__ float  g_plsum[4*64*1024];      // partial weight sums per split
// packed weight pairs (reduction-dim interleaved -> direct b64 FFMA2 operands)
__device__ unsigned long long g_Wp64[8*64*16];    // [h][ip][d]
__device__ unsigned long long g_w1p64[64*256];    // [ip][c]
__device__ unsigned long long g_w2p64[128*128];   // [kp][c]

__device__ __forceinline__ unsigned long long pk2(float a, float b){
    unsigned long long r;
    asm("mov.b64 %0, {%1, %2};" : "=l"(r) : "f"(a), "f"(b));
    return r;
}
__device__ __forceinline__ void fma2(unsigned long long &d, unsigned long long a, unsigned long long b){
    asm("fma.rn.f32x2 %0, %1, %2, %0;" : "+l"(d) : "l"(a), "l"(b));
}
__device__ __forceinline__ float2 upk(unsigned long long v){
    float2 r;
    asm("mov.b64 {%0, %1}, %2;" : "=f"(r.x), "=f"(r.y) : "l"(v));
    return r;
}

// ---------------------------------------------------------------------------
// K00: pack weight matrices into reduction-dim-pair layout.
// ---------------------------------------------------------------------------
__global__ void __launch_bounds__(256) k00_pack(const float* __restrict__ W,
                                                const float* __restrict__ w1,
                                                const float* __restrict__ w2)
{
    int i = blockIdx.x*256 + threadIdx.x;
    if (i < 8192){
        int h = i >> 10, rem = i & 1023, ip = rem >> 4, d = rem & 15;
        g_Wp64[i] = pk2(W[h*2048 + (2*ip)*16 + d], W[h*2048 + (2*ip+1)*16 + d]);
        return;
    }
    int j = i - 8192;
    if (j < 16384){
        int ip = j >> 8, c = j & 255;
        g_w1p64[j] = pk2(w1[(2*ip)*256 + c], w1[(2*ip+1)*256 + c]);
        return;
    }
    int k = j - 16384;
    if (k < 16384){
        int kp = k >> 7, c = k & 127;
        g_w2p64[k] = pk2(w2[(2*kp)*128 + c], w2[(2*kp+1)*128 + c]);
    }
}

// ---------------------------------------------------------------------------
// K1: Wh = h@W (packed pairs, FFMA2) + factorized-softmax exp tables
//     + adjacency bit-packing (merged former k0; overlaps its HBM read).
// grid 1024 x 128; block = 8 rows.
// ---------------------------------------------------------------------------
__global__ void __launch_bounds__(128) k1_wh(const float* __restrict__ h,
                                             const float* __restrict__ a,
                                             const int* __restrict__ adj)
{
    __shared__ __align__(16) float hs[8][128];
    __shared__ __align__(16) float ps[8][128];
    __shared__ __align__(16) float qs[8][128];
    const int tid = threadIdx.x;
    const int warp = tid >> 5, lane = tid & 31;
    const int gr0 = blockIdx.x * 8;
    {
        const float4* src = (const float4*)(h + gr0*128);
        float4* dst = (float4*)hs;
        #pragma unroll
        for (int q=0;q<2;q++) dst[q*128 + tid] = src[q*128 + tid];
    }

    // pack adjacency bits for this block's 8 rows (warp w: rows 2w, 2w+1)
    {
        #pragma unroll
        for (int rr=0; rr<2; rr++){
            int grow = gr0 + warp*2 + rr;
            const int* rp = adj + (size_t)grow * 1024;
            unsigned* op  = g_mb + grow * 32;
            #pragma unroll 4
            for (int wd=0; wd<32; wd++){
                unsigned v = __ballot_sync(0xffffffffu, rp[wd*32 + lane] != 0);
                if (lane == 0) op[wd] = v;
            }
        }
    }

    __syncthreads();
    const int hh = tid >> 4, d = tid & 15;
    const unsigned long long* wp = g_Wp64 + hh*1024 + d;
    unsigned long long acc[8];
    #pragma unroll
    for (int r=0;r<8;r++) acc[r] = 0ull;
    #pragma unroll 4
    for (int ip2=0; ip2<32; ip2++){
        unsigned long long wv0 = __ldg(wp + ip2*32);
        unsigned long long wv1 = __ldg(wp + ip2*32 + 16);
        #pragma unroll
        for (int r=0;r<8;r++){
            ulonglong2 hv = *(const ulonglong2*)&hs[r][ip2*4];
            fma2(acc[r], hv.x, wv0);
            fma2(acc[r], hv.y, wv1);
        }
    }
    const float asrc = __ldg(a + hh*32 + d);
    const float adst = __ldg(a + hh*32 + 16 + d);
    #pragma unroll
    for (int r=0;r<8;r++){
        float2 v = upk(acc[r]);
        float val = v.x + v.y;
        g_Wh[(gr0+r)*128 + tid] = val;
        ps[r][tid] = val*asrc;
        qs[r][tid] = val*adst;
    }
    __syncthreads();

    if (tid < 64){
        const int rr = tid >> 3, hh2 = tid & 7;
        const float4* pp = (const float4*)&ps[rr][hh2*16];
        const float4* qq = (const float4*)&qs[rr][hh2*16];
        float4 a0=pp[0], a1=pp[1], a2=pp[2], a3=pp[3];
        float4 b0=qq[0], b1=qq[1], b2=qq[2], b3=qq[3];
        float si = ((a0.x+a0.y)+(a0.z+a0.w)) + ((a1.x+a1.y)+(a1.z+a1.w))
                 + ((a2.x+a2.y)+(a2.z+a2.w)) + ((a3.x+a3.y)+(a3.z+a3.w));
        float sj = ((b0.x+b0.y)+(b0.z+b0.w)) + ((b1.x+b1.y)+(b1.z+b1.w))
                 + ((b2.x+b2.y)+(b2.z+b2.w)) + ((b3.x+b3.y)+(b3.z+b3.w));
        si *= L2E; sj *= L2E;
        const int b  = gr0 >> 10;
        const int n0 = gr0 & 1023;
        const int idx = (b*8 + hh2)*1024 + n0 + rr;
        g_p[idx] = make_float4(exp2f(si), exp2f(0.2f*si), 0.f, 0.f);
        g_q[idx] = make_float2(exp2f(sj), exp2f(0.2f*sj));
    }
}

// ---------------------------------------------------------------------------
// K2: fused masked-softmax attention, MUFU-free, 2 rows/lane.
// Block: 64 rows x 4 heads x 256 keys (4-way key split); 8 warps.
// Weight via exact max identity: w = max(p1*q1, p2*q2)  [exp2 monotone]
// __launch_bounds__(256,3): 3 CTAs/SM (24 warps) -- measured optimum.
// ---------------------------------------------------------------------------
__global__ void __launch_bounds__(256, 3) k2_attn()
{
    __shared__ __align__(16) float Whs[128][64];
    __shared__ __align__(16) float2 qt[4][128];
    __shared__ unsigned mbits[64][9];
    const int tid  = threadIdx.x;
    const int warp = tid >> 5, lane = tid & 31;
    const int hw = warp & 3, grp = warp >> 2;
    const int nt = blockIdx.x;
    const int hb = blockIdx.y & 1, sp = blockIdx.y >> 1;   // sp in [0,4)
    const int b  = blockIdx.z;
    const int h    = hb*4 + hw;
    const int row0 = nt*64 + lane;
    const int row1 = row0 + 32;
    const int key0 = sp*256;

    {
        #pragma unroll
        for (int q=0;q<2;q++){
            int lin = q*256 + tid;
            int rr = lin >> 3, ww = lin & 7;
            mbits[rr][ww] = g_mb[(b*1024 + nt*64 + rr)*32 + sp*8 + ww];
        }
    }

    const float4 pva = g_p[(b*8+h)*1024 + row0];
    const float4 pvb = g_p[(b*8+h)*1024 + row1];
    const float p1a = pva.x, p2a = pva.y;
    const float p1b = pvb.x, p2b = pvb.y;

    unsigned long long acc0[8], acc1[8];
    #pragma unroll
    for (int j=0;j<8;j++){ acc0[j] = 0ull; acc1[j] = 0ull; }
    float lsum0 = 0.f, lsum1 = 0.f;

    const int bhq = b*8 + hb*4;
    #pragma unroll
    for (int mt=0; mt<2; mt++){
        __syncthreads();
        {
            const float* base = g_Wh + ((size_t)(b<<10))*128 + hb*64;
            #pragma unroll
            for (int q=0;q<8;q++){
                int lin = q*256 + tid;
                int r = lin >> 4, c4 = lin & 15;
                int key = key0 + mt*64 + ((r < 64) ? r : r + 64);
                ((float4*)Whs)[lin] = ((const float4*)(base + key*128))[c4];
            }
            #pragma unroll
            for (int q=0;q<2;q++){
                int lin = q*256 + tid;
                int hl = lin >> 7, k128 = lin & 127;
                int key = key0 + mt*64 + ((k128 < 64) ? k128 : k128 + 64);
                qt[hl][k128] = g_q[(bhq+hl)*1024 + key];
            }
        }
        __syncthreads();
        const float2* qp = &qt[hw][grp*64];
        const float*  wb = &Whs[grp*64][0] + hw*16;
        #pragma unroll
        for (int k=0;k<2;k++){
            unsigned mw0 = mbits[lane][grp*4 + mt*2 + k];
            unsigned mw1 = mbits[lane+32][grp*4 + mt*2 + k];
            #pragma unroll
            for (int j=0;j<32;j++){
                int m = k*32 + j;
                float2 q = qp[m];
                const ulonglong2* wv = (const ulonglong2*)(wb + m*64);
                ulonglong2 v0 = wv[0];
                ulonglong2 v1 = wv[1];
                ulonglong2 v2 = wv[2];
                ulonglong2 v3 = wv[3];
                // row 0: exact select == max (exp2 monotone)
                float ta = fmaxf(p1a*q.x, p2a*q.y);
                float wa = (mw0 & (1u<<j)) ? ta : 0.f;
                lsum0 += wa;
                unsigned long long wwa = pk2(wa, wa);
                fma2(acc0[0], v0.x, wwa);
                fma2(acc0[1], v0.y, wwa);
                fma2(acc0[2], v1.x, wwa);
                fma2(acc0[3], v1.y, wwa);
                fma2(acc0[4], v2.x, wwa);
                fma2(acc0[5], v2.y, wwa);
                fma2(acc0[6], v3.x, wwa);
                fma2(acc0[7], v3.y, wwa);
                // row 1
                float tb = fmaxf(p1b*q.x, p2b*q.y);
                float wbv = (mw1 & (1u<<j)) ? tb : 0.f;
                lsum1 += wbv;
                unsigned long long wwb = pk2(wbv, wbv);
                fma2(acc1[0], v0.x, wwb);
                fma2(acc1[1], v0.y, wwb);
                fma2(acc1[2], v1.x, wwb);
                fma2(acc1[3], v1.y, wwb);
                fma2(acc1[4], v2.x, wwb);
                fma2(acc1[5], v2.y, wwb);
                fma2(acc1[6], v3.x, wwb);
                fma2(acc1[7], v3.y, wwb);
            }
        }
    }

    __syncthreads();
    unsigned long long (*red)[64][9] = (unsigned long long(*)[64][9])Whs;
    if (grp == 1){
        #pragma unroll
        for (int j=0;j<8;j++){
            red[hw][lane][j]    = acc0[j];
            red[hw][lane+32][j] = acc1[j];
        }
        red[hw][lane][8]    = pk2(lsum0, 0.f);
        red[hw][lane+32][8] = pk2(lsum1, 0.f);
    }
    __syncthreads();
    if (grp == 0){
        lsum0 += upk(red[hw][lane][8]).x;
        lsum1 += upk(red[hw][lane+32][8]).x;
        g_plsum[(sp*64 + b*8 + h)*1024 + row0] = lsum0;
        g_plsum[(sp*64 + b*8 + h)*1024 + row1] = lsum1;
        float* out0 = g_patt + ((size_t)((sp<<13) + (b<<10) + row0))*128 + h*16;
        float* out1 = g_patt + ((size_t)((sp<<13) + (b<<10) + row1))*128 + h*16;
        #pragma unroll
        for (int j=0;j<4;j++){
            float2 pa0 = upk(acc0[j*2]);
            float2 pa1 = upk(acc0[j*2+1]);
            float2 pb0 = upk(red[hw][lane][j*2]);
            float2 pb1 = upk(red[hw][lane][j*2+1]);
            ((float4*)out0)[j] = make_float4(pa0.x+pb0.x, pa0.y+pb0.y,
                                             pa1.x+pb1.x, pa1.y+pb1.y);
        }
        #pragma unroll
        for (int j=0;j<4;j++){
            float2 pa0 = upk(acc1[j*2]);
            float2 pa1 = upk(acc1[j*2+1]);
            float2 pb0 = upk(red[hw][lane+32][j*2]);
            float2 pb1 = upk(red[hw][lane+32][j*2+1]);
            ((float4*)out1)[j] = make_float4(pa0.x+pb0.x, pa0.y+pb0.y,
                                             pa1.x+pb1.x, pa1.y+pb1.y);
        }
    }
}

// ---------------------------------------------------------------------------
// K3: combine attention partials + LN1 -> FFN -> LN2.
// 128 threads x 8 rows, grid 1024. Weights via coalesced LDG.128.
// Stage-2 AND stage-3 unrolled to 8 for LDG MLP.
// ---------------------------------------------------------------------------
__global__ void __launch_bounds__(128) k3_ffn(
    const float* __restrict__ h,
    const float* __restrict__ ln1g, const float* __restrict__ ln1b,
    const float* __restrict__ b1,
    const float* __restrict__ b2,
    const float* __restrict__ ln2g, const float* __restrict__ ln2b,
    float* __restrict__ out)
{
    __shared__ __align__(16) float hcs[8][128];
    __shared__ __align__(16) float mids[8][256];
    const int tid = threadIdx.x;
    const int gr0 = blockIdx.x * 8;
    const int r = tid >> 4, l16 = tid & 15;
    const int gr = gr0 + r;

    // Stage 1: combine split partials, divide, add residual, LN1 -> hcs
    float x[8];
    {
        const int head = l16 >> 1;
        const int bb = gr >> 10, rw = gr & 1023;
        float lsum = 0.f;
        #pragma unroll
        for (int s=0;s<4;s++) lsum += g_plsum[(s*64 + bb*8 + head)*1024 + rw];
        float inv = (lsum > 0.f) ? __fdividef(1.f, lsum) : 0.f;

        float4 a0 = make_float4(0,0,0,0), a1 = make_float4(0,0,0,0);
        #pragma unroll
        for (int s=0;s<4;s++){
            const float4* pp = (const float4*)(g_patt + ((size_t)((s<<13) + gr))*128 + l16*8);
            float4 t0 = pp[0], t1 = pp[1];
            a0.x+=t0.x; a0.y+=t0.y; a0.z+=t0.z; a0.w+=t0.w;
            a1.x+=t1.x; a1.y+=t1.y; a1.z+=t1.z; a1.w+=t1.w;
        }
        const float4* hp = (const float4*)(h + gr*128 + l16*8);
        float4 h0 = hp[0], h1 = hp[1];
        x[0]=fmaf(a0.x,inv,h0.x); x[1]=fmaf(a0.y,inv,h0.y);
        x[2]=fmaf(a0.z,inv,h0.z); x[3]=fmaf(a0.w,inv,h0.w);
        x[4]=fmaf(a1.x,inv,h1.x); x[5]=fmaf(a1.y,inv,h1.y);
        x[6]=fmaf(a1.z,inv,h1.z); x[7]=fmaf(a1.w,inv,h1.w);
    }
    float s=0.f, sq=0.f;
    #pragma unroll
    for (int i=0;i<8;i++){ s += x[i]; sq = fmaf(x[i],x[i],sq); }
    #pragma unroll
    for (int o=8;o;o>>=1){
        s  += __shfl_xor_sync(0xffffffffu, s,  o);
        sq += __shfl_xor_sync(0xffffffffu, sq, o);
    }
    float mu   = s * 0.0078125f;
    float var  = fmaf(sq, 0.0078125f, -mu*mu);
    float rstd = rsqrtf(var + 1e-5f);
    #pragma unroll
    for (int i=0;i<8;i++){
        int c = l16*8 + i;
        hcs[r][c] = (x[i]-mu)*rstd*__ldg(ln1g+c) + __ldg(ln1b+c);
    }
    __syncthreads();

    // Stage 2: mids = relu(hc @ w1 + b1). thread = colpair cp, 8 rows.
    {
        const int cp = tid;                 // cols 2cp, 2cp+1
        unsigned long long acc[8][2];
        #pragma unroll
        for (int rr=0;rr<8;rr++){ acc[rr][0]=0ull; acc[rr][1]=0ull; }
        #pragma unroll 8
        for (int ip2=0; ip2<32; ip2++){
            ulonglong2 w0 = __ldg((const ulonglong2*)(g_w1p64 + (2*ip2  )*256 + 2*cp));
            ulonglong2 w1v= __ldg((const ulonglong2*)(g_w1p64 + (2*ip2+1)*256 + 2*cp));
            #pragma unroll
            for (int rr=0;rr<8;rr++){
                ulonglong2 hv = *(const ulonglong2*)&hcs[rr][ip2*4];
                fma2(acc[rr][0], hv.x, w0.x);
                fma2(acc[rr][1], hv.x, w0.y);
                fma2(acc[rr][0], hv.y, w1v.x);
                fma2(acc[rr][1], hv.y, w1v.y);
            }
        }
        float2 bb = __ldg((const float2*)b1 + cp);
        #pragma unroll
        for (int rr=0;rr<8;rr++){
            float2 s0 = upk(acc[rr][0]);
            float2 s1 = upk(acc[rr][1]);
            float m0 = fmaxf(s0.x + s0.y + bb.x, 0.f);
            float m1 = fmaxf(s1.x + s1.y + bb.y, 0.f);
            *(float2*)&mids[rr][cp*2] = make_float2(m0, m1);
        }
    }
    __syncthreads();

    // Stage 3: z = hc + mid @ w2 + b2 (in place). thread = (row-half, colpair).
    {
        const int rg = tid >> 6;            // 0..1 -> rows rg*4 .. +3
        const int cp = tid & 63;            // cols 2cp, 2cp+1
        unsigned long long acc[4][2];
        #pragma unroll
        for (int rr=0;rr<4;rr++){ acc[rr][0]=0ull; acc[rr][1]=0ull; }
        #pragma unroll 8
        for (int kp2=0; kp2<64; kp2++){
            ulonglong2 w0 = __ldg((const ulonglong2*)(g_w2p64 + (2*kp2  )*128 + 2*cp));
            ulonglong2 w1v= __ldg((const ulonglong2*)(g_w2p64 + (2*kp2+1)*128 + 2*cp));
            #pragma unroll
            for (int rr=0;rr<4;rr++){
                ulonglong2 mv = *(const ulonglong2*)&mids[rg*4+rr][kp2*4];
                fma2(acc[rr][0], mv.x, w0.x);
                fma2(acc[rr][1], mv.x, w0.y);
                fma2(acc[rr][0], mv.y, w1v.x);
                fma2(acc[rr][1], mv.y, w1v.y);
            }
        }
        float2 bb = __ldg((const float2*)b2 + cp);
        #pragma unroll
        for (int rr=0;rr<4;rr++){
            int rw = rg*4 + rr;
            float2 hv = *(const float2*)&hcs[rw][cp*2];
            float2 s0 = upk(acc[rr][0]);
            float2 s1 = upk(acc[rr][1]);
            float z0 = hv.x + s0.x + s0.y + bb.x;
            float z1 = hv.y + s1.x + s1.y + bb.y;
            *(float2*)&hcs[rw][cp*2] = make_float2(z0, z1);
        }
    }
    __syncthreads();

    // Stage 4: LN2 -> out
    float z[8];
    #pragma unroll
    for (int i=0;i<8;i++) z[i] = hcs[r][l16*8+i];
    float s2=0.f, sq2=0.f;
    #pragma unroll
    for (int i=0;i<8;i++){ s2 += z[i]; sq2 = fmaf(z[i],z[i],sq2); }
    #pragma unroll
    for (int o=8;o;o>>=1){
        s2  += __shfl_xor_sync(0xffffffffu, s2,  o);
        sq2 += __shfl_xor_sync(0xffffffffu, sq2, o);
    }
    float mu2   = s2 * 0.0078125f;
    float var2  = fmaf(sq2, 0.0078125f, -mu2*mu2);
    float rstd2 = rsqrtf(var2 + 1e-5f);
    float t[8];
    #pragma unroll
    for (int i=0;i<8;i++){
        int c = l16*8+i;
        t[i] = (z[i]-mu2)*rstd2*__ldg(ln2g+c) + __ldg(ln2b+c);
    }
    float* op = out + gr*128 + l16*8;
    ((float4*)op)[0] = make_float4(t[0],t[1],t[2],t[3]);
    ((float4*)op)[1] = make_float4(t[4],t[5],t[6],t[7]);
}

// ---------------------------------------------------------------------------
extern "C" void kernel_launch(void* const* d_in, const int* in_sizes, int n_in,
                              void* d_out, int out_size)
{
    const float* h    = (const float*)d_in[0];
    const int*   adj  = (const int*  )d_in[1];
    const float* W    = (const float*)d_in[2];
    const float* a    = (const float*)d_in[3];
    const float* ln1g = (const float*)d_in[4];
    const float* ln1b = (const float*)d_in[5];
    const float* w1   = (const float*)d_in[6];
    const float* b1   = (const float*)d_in[7];
    const float* w2   = (const float*)d_in[8];
    const float* b2   = (const float*)d_in[9];
    const float* ln2g = (const float*)d_in[10];
    const float* ln2b = (const float*)d_in[11];
    float* out = (float*)d_out;

    k00_pack<<<160, 256>>>(W, w1, w2);
    k1_wh<<<1024, 128>>>(h, a, adj);
    k2_attn<<<dim3(16, 8, 8), 256>>>();
    k3_ffn<<<1024, 128>>>(h, ln1g, ln1b, b1, b2, ln2g, ln2b, out);
}